// round 1
// baseline (speedup 1.0000x reference)
#include <cuda_runtime.h>

#define NPTS 4096
#define BQ_K 32
#define M_PER_B (NPTS * BQ_K)   // 131072 columns per batch
#define NBATCH 2

// ---------------- scratch (device globals; no allocations) ----------------
__device__ float g_x0[NBATCH * 13  * M_PER_B];   // fused features, [b][c][m]
__device__ float g_x1[NBATCH * 64  * M_PER_B];   // conv0 out (raw, pre-GN)
__device__ float g_x2[NBATCH * 64  * M_PER_B];   // conv1 out (raw, pre-GN)
__device__ float g_mx[NBATCH * 128 * NPTS];      // max over k of conv2 out (raw)
__device__ float g_mn[NBATCH * 128 * NPTS];      // min over k of conv2 out (raw)
__device__ float g_part[3][NBATCH * 512 * 8 * 2]; // per-block GN partial sums
__device__ float g_mr[3][NBATCH * 8 * 2];        // per-(b,group) mean/rstd

// ---------------- helpers ----------------
__device__ __forceinline__ float lo32(unsigned long long v) {
    return __uint_as_float((unsigned)(v & 0xffffffffull));
}
__device__ __forceinline__ float hi32(unsigned long long v) {
    return __uint_as_float((unsigned)(v >> 32));
}
// packed fp32x2 FMA (sm_103a): a = w*y + a, elementwise on two packed floats
__device__ __forceinline__ void ffma2(unsigned long long& a,
                                      unsigned long long w,
                                      unsigned long long y) {
    asm("fma.rn.f32x2 %0, %1, %2, %0;" : "+l"(a) : "l"(w), "l"(y));
}

__device__ __forceinline__ float angle3(float ax, float ay, float az,
                                        float bx, float by, float bz) {
    float cx = ay * bz - az * by;
    float cy = az * bx - ax * bz;
    float cz = ax * by - ay * bx;
    float s = cx * cx + cy * cy + cz * cz;
    float y = s > 0.f ? sqrtf(s) : 0.f;
    float x = ax * bx + ay * by + az * bz;
    if (y == 0.f && x == 0.f) return 0.f;
    return atan2f(y, x);
}

// ---------------- kernel 1: ball query + fused 13-ch features ----------------
// grid (512, 2), 256 threads. Warp per point; xyz of whole batch in smem.
__global__ void __launch_bounds__(256) ball_feat_kernel(
    const float* __restrict__ xyz, const float* __restrict__ feat,
    const float* __restrict__ wa, const float* __restrict__ wb,
    const float* __restrict__ wc)
{
    __shared__ float sx[NPTS * 3];  // 48KB
    const int b = blockIdx.y;
    const float* xb = xyz + (size_t)b * NPTS * 3;
    const float* fb = feat + (size_t)b * NPTS * 3;
    for (int i = threadIdx.x; i < NPTS * 3; i += 256) sx[i] = xb[i];
    __syncthreads();

    const int warp = threadIdx.x >> 5;
    const int lane = threadIdx.x & 31;
    const int i = blockIdx.x * 8 + warp;

    const float cx = sx[i * 3 + 0], cy = sx[i * 3 + 1], cz = sx[i * 3 + 2];
    const float R2 = (float)(0.1 * 0.1);   // matches f32(radius*radius)

    int myj = 0;
    int found = 0;
    for (int jb = 0; jb < NPTS; jb += 32) {
        int j = jb + lane;
        float dx = sx[j * 3 + 0] - cx;
        float dy = sx[j * 3 + 1] - cy;
        float dz = sx[j * 3 + 2] - cz;
        // no FMA contraction: match XLA's mul+add rounding at the boundary
        float d2 = __fadd_rn(__fadd_rn(__fmul_rn(dx, dx), __fmul_rn(dy, dy)),
                             __fmul_rn(dz, dz));
        unsigned m = __ballot_sync(0xffffffffu, d2 <= R2);
        int cnt = __popc(m);
        if (lane >= found && lane < found + cnt) {
            int pos = __fns(m, 0, lane - found + 1);
            myj = jb + pos;
        }
        found += cnt;
        if (found >= BQ_K) break;
    }
    int j0 = __shfl_sync(0xffffffffu, myj, 0);   // smallest in-radius index
    if (lane >= found) myj = j0;                 // pad with first

    // features for slot k = lane
    float gx = sx[myj * 3 + 0], gy = sx[myj * 3 + 1], gz = sx[myj * 3 + 2];
    float nx = __ldg(fb + myj * 3 + 0), ny = __ldg(fb + myj * 3 + 1), nz = __ldg(fb + myj * 3 + 2);
    float rx = __ldg(fb + i * 3 + 0),  ry = __ldg(fb + i * 3 + 1),  rz = __ldg(fb + i * 3 + 2);
    float dx = gx - cx, dy = gy - cy, dz = gz - cz;
    float sq = dx * dx + dy * dy + dz * dz;
    float dist = sq > 0.f ? sqrtf(sq) : 0.f;
    float a1 = angle3(rx, ry, rz, dx, dy, dz);
    float a2 = angle3(nx, ny, nz, dx, dy, dz);
    float a3 = angle3(rx, ry, rz, nx, ny, nz);
    float A = __ldg(wa), Bv = __ldg(wb), Cv = __ldg(wc);

    float* o = g_x0 + (size_t)b * 13 * M_PER_B + (size_t)i * 32 + lane;
    o[0 * M_PER_B]  = A * cx;  o[1 * M_PER_B]  = A * cy;  o[2 * M_PER_B]  = A * cz;
    o[3 * M_PER_B]  = A * gx;  o[4 * M_PER_B]  = A * gy;  o[5 * M_PER_B]  = A * gz;
    o[6 * M_PER_B]  = Bv * dx; o[7 * M_PER_B]  = Bv * dy; o[8 * M_PER_B]  = Bv * dz;
    o[9 * M_PER_B]  = Bv * dist;
    o[10 * M_PER_B] = Cv * a1; o[11 * M_PER_B] = Cv * a2; o[12 * M_PER_B] = Cv * a3;
}

// ---------------- fused GEMM + (input GN/ReLU) + stats (+ max/min epilogue) ----
// LAYER 0: 13->64  (no input GN)     -> g_x1 + stats0
// LAYER 1: 64->64  (GN0+ReLU input)  -> g_x2 + stats1
// LAYER 2: 64->128 (GN1+ReLU input)  -> max/min over k + stats2
template <int LAYER>
__global__ void __launch_bounds__(LAYER == 2 ? 512 : 256, 1) gemm_gn_kernel(
    const float* __restrict__ W, const float* __restrict__ gamma,
    const float* __restrict__ beta)
{
    constexpr int C     = (LAYER == 0) ? 13 : 64;
    constexpr int O     = (LAYER == 2) ? 128 : 64;
    constexpr int NT    = (O / 16) * 64;          // 256 or 512 threads
    constexpr int NW    = NT / 32;
    constexpr int CHUNK = (LAYER == 2) ? 8 : 16;
    constexpr bool GN_IN = (LAYER > 0);
    constexpr bool LAST  = (LAYER == 2);
    constexpr int GPB   = 128 / O;                // group slots per 16-out block

    extern __shared__ unsigned char smraw[];
    float2* Wp      = (float2*)smraw;                               // [O*C] {w,w}
    float*  Xs      = (float*)(smraw + sizeof(float2) * O * C);     // [CHUNK][256]
    float*  sScale  = Xs + CHUNK * 256;                             // [C]
    float*  sShift  = sScale + C;                                   // [C]
    float*  sWsum   = sShift + C;                                   // [NW][2][2]

    const int tid = threadIdx.x;
    const int b   = blockIdx.y;
    const int m0  = blockIdx.x * 256;

    for (int idx = tid; idx < O * C; idx += NT) {
        float w = W[idx];
        Wp[idx] = make_float2(w, w);
    }
    if (GN_IN) {
        if (tid < C) {
            const float* mr = g_mr[(LAYER > 0) ? LAYER - 1 : 0] + b * 16;
            int gg = tid / (C / 8);
            float s = mr[gg * 2 + 1] * gamma[tid];
            sScale[tid] = s;
            sShift[tid] = beta[tid] - mr[gg * 2] * s;
        }
    }

    const int ob = tid >> 6;      // 16-output block
    const int cg = tid & 63;      // column group (4 columns)
    const int lane = tid & 31;
    const int wrp  = tid >> 5;

    unsigned long long acc[16][2];
#pragma unroll
    for (int a = 0; a < 16; a++) { acc[a][0] = 0ull; acc[a][1] = 0ull; }

    const float* xin = (LAYER == 0) ? g_x0 : ((LAYER == 1) ? g_x1 : g_x2);
    const float* xbp = xin + (size_t)b * C * M_PER_B + m0;
    const unsigned long long* wbase = (const unsigned long long*)Wp;

    for (int cc = 0; cc < C; cc += CHUNK) {
        __syncthreads();
        for (int idx = tid; idx < CHUNK * 256; idx += NT) {
            int ci  = cc + (idx >> 8);
            int col = idx & 255;
            if (ci < C) {
                float v = xbp[(size_t)ci * M_PER_B + col];
                if (GN_IN) v = fmaxf(sScale[ci] * v + sShift[ci], 0.f);
                Xs[idx] = v;
            }
        }
        __syncthreads();
#pragma unroll
        for (int i = 0; i < CHUNK; i++) {
            if (cc + i >= C) break;
            const ulonglong2 y = *(const ulonglong2*)&Xs[i * 256 + cg * 4];
            const unsigned long long* wrow = wbase + (size_t)(ob * 16) * C + cc + i;
#pragma unroll
            for (int oo = 0; oo < 16; oo++) {
                unsigned long long w = wrow[(size_t)oo * C];
                ffma2(acc[oo][0], w, y.x);
                ffma2(acc[oo][1], w, y.y);
            }
        }
    }

    // ---- epilogue: store (mid) or max/min over k (last) ----
    if (!LAST) {
        float* xo = ((LAYER == 0) ? g_x1 : g_x2) + (size_t)b * O * M_PER_B + m0;
#pragma unroll
        for (int oo = 0; oo < 16; oo++) {
            float4 v;
            v.x = lo32(acc[oo][0]); v.y = hi32(acc[oo][0]);
            v.z = lo32(acc[oo][1]); v.w = hi32(acc[oo][1]);
            *(float4*)&xo[(size_t)(ob * 16 + oo) * M_PER_B + cg * 4] = v;
        }
    } else {
        // columns m = n*32+k; this thread's 4 columns are 4 k's of one n;
        // 8 consecutive lanes (cg bits 0..2) cover all 32 k of that n.
        int nloc = cg >> 3;
        int n = blockIdx.x * 8 + nloc;
#pragma unroll
        for (int oo = 0; oo < 16; oo++) {
            float v0 = lo32(acc[oo][0]), v1 = hi32(acc[oo][0]);
            float v2 = lo32(acc[oo][1]), v3 = hi32(acc[oo][1]);
            float mx = fmaxf(fmaxf(v0, v1), fmaxf(v2, v3));
            float mn = fminf(fminf(v0, v1), fminf(v2, v3));
#pragma unroll
            for (int d = 1; d < 8; d <<= 1) {
                mx = fmaxf(mx, __shfl_xor_sync(0xffffffffu, mx, d));
                mn = fminf(mn, __shfl_xor_sync(0xffffffffu, mn, d));
            }
            if ((lane & 7) == 0) {
                int o = ob * 16 + oo;
                g_mx[((size_t)b * O + o) * NPTS + n] = mx;
                g_mn[((size_t)b * O + o) * NPTS + n] = mn;
            }
        }
    }

    // ---- GN stats partials (deterministic: shuffle + fixed-order tree) ----
#pragma unroll
    for (int s = 0; s < GPB; s++) {
        float S = 0.f, Q = 0.f;
#pragma unroll
        for (int oo = s * (16 / GPB); oo < (s + 1) * (16 / GPB); oo++) {
#pragma unroll
            for (int p = 0; p < 2; p++) {
                float v0 = lo32(acc[oo][p]), v1 = hi32(acc[oo][p]);
                S += v0 + v1;
                Q += v0 * v0 + v1 * v1;
            }
        }
#pragma unroll
        for (int d = 16; d > 0; d >>= 1) {
            S += __shfl_xor_sync(0xffffffffu, S, d);
            Q += __shfl_xor_sync(0xffffffffu, Q, d);
        }
        if (lane == 0) {
            sWsum[(wrp * 2 + s) * 2 + 0] = S;
            sWsum[(wrp * 2 + s) * 2 + 1] = Q;
        }
    }
    __syncthreads();
    if (tid < 8) {   // tid = group id g (NUM_GROUPS = 8)
        float S, Q;
        if (O == 64) {               // group g -> ob=g>>1, slot=g&1, warps {2ob,2ob+1}
            int ob2 = tid >> 1, s = tid & 1;
            int w0 = 2 * ob2, w1 = 2 * ob2 + 1;
            S = sWsum[(w0 * 2 + s) * 2 + 0] + sWsum[(w1 * 2 + s) * 2 + 0];
            Q = sWsum[(w0 * 2 + s) * 2 + 1] + sWsum[(w1 * 2 + s) * 2 + 1];
        } else {                     // O=128: group g = ob, warps {2g,2g+1}, slot 0
            int w0 = 2 * tid, w1 = 2 * tid + 1;
            S = sWsum[(w0 * 2) * 2 + 0] + sWsum[(w1 * 2) * 2 + 0];
            Q = sWsum[(w0 * 2) * 2 + 1] + sWsum[(w1 * 2) * 2 + 1];
        }
        float* pp = g_part[LAYER] + (((size_t)b * gridDim.x + blockIdx.x) * 8 + tid) * 2;
        pp[0] = S;
        pp[1] = Q;
    }
}

// ---------------- per-(b,group) stats reduce ----------------
template <int LAYER>
__global__ void __launch_bounds__(256) reduce_stats_kernel()
{
    constexpr float INV = (LAYER == 2) ? (1.f / 2097152.f) : (1.f / 1048576.f);
    const int b = blockIdx.x >> 3, g = blockIdx.x & 7;
    __shared__ float sS[256], sQ[256];
    float S = 0.f, Q = 0.f;
    for (int mb = threadIdx.x; mb < 512; mb += 256) {
        const float* p = g_part[LAYER] + (((size_t)b * 512 + mb) * 8 + g) * 2;
        S += p[0];
        Q += p[1];
    }
    sS[threadIdx.x] = S; sQ[threadIdx.x] = Q;
    __syncthreads();
    for (int d = 128; d > 0; d >>= 1) {
        if (threadIdx.x < d) {
            sS[threadIdx.x] += sS[threadIdx.x + d];
            sQ[threadIdx.x] += sQ[threadIdx.x + d];
        }
        __syncthreads();
    }
    if (threadIdx.x == 0) {
        float mean = sS[0] * INV;
        float var  = sQ[0] * INV - mean * mean;
        g_mr[LAYER][b * 16 + g * 2 + 0] = mean;
        g_mr[LAYER][b * 16 + g * 2 + 1] = rsqrtf(var + 1e-5f);
    }
}

// ---------------- finalize: apply GN2 affine to max/min, emit (out, x) -------
__global__ void __launch_bounds__(256) finalize_kernel(
    const float* __restrict__ gamma, const float* __restrict__ beta,
    float* __restrict__ out)
{
    int i = blockIdx.x * 256 + threadIdx.x;       // [b][o][n], 2*128*4096
    int o = (i >> 12) & 127;
    int b = i >> 19;
    int g = o >> 4;
    const float* mr = g_mr[2] + b * 16 + g * 2;
    float s = mr[1] * gamma[o];
    float t = beta[o] - mr[0] * s;
    float v = (s >= 0.f) ? (s * g_mx[i] + t) : (s * g_mn[i] + t);
    out[i] = fmaxf(v, 0.f);                        // out = max_k relu(y)
    out[2 * 128 * NPTS + i] = v;                   // x   = max_k y
}

// ---------------- launch ----------------
extern "C" void kernel_launch(void* const* d_in, const int* in_sizes, int n_in,
                              void* d_out, int out_size)
{
    const float* feature = (const float*)d_in[0];
    const float* xyz     = (const float*)d_in[1];
    const float* w0  = (const float*)d_in[2];
    const float* gg0 = (const float*)d_in[3];
    const float* gb0 = (const float*)d_in[4];
    const float* w1  = (const float*)d_in[5];
    const float* gg1 = (const float*)d_in[6];
    const float* gb1 = (const float*)d_in[7];
    const float* w2  = (const float*)d_in[8];
    const float* gg2 = (const float*)d_in[9];
    const float* gb2 = (const float*)d_in[10];
    const float* wa  = (const float*)d_in[11];
    const float* wb  = (const float*)d_in[12];
    const float* wc  = (const float*)d_in[13];
    float* out = (float*)d_out;

    // dynamic smem: Wp(O*C*8) + Xs(CHUNK*256*4) + scale/shift(2C*4) + sWsum(NW*16)
    const int sm0 = 64 * 13 * 8 + 16 * 256 * 4 + 2 * 13 * 4 + 8 * 16 + 256;
    const int sm1 = 64 * 64 * 8 + 16 * 256 * 4 + 2 * 64 * 4 + 8 * 16 + 256;
    const int sm2 = 128 * 64 * 8 + 8 * 256 * 4 + 2 * 64 * 4 + 16 * 16 + 256;
    cudaFuncSetAttribute(gemm_gn_kernel<0>, cudaFuncAttributeMaxDynamicSharedMemorySize, sm0);
    cudaFuncSetAttribute(gemm_gn_kernel<1>, cudaFuncAttributeMaxDynamicSharedMemorySize, sm1);
    cudaFuncSetAttribute(gemm_gn_kernel<2>, cudaFuncAttributeMaxDynamicSharedMemorySize, sm2);

    ball_feat_kernel<<<dim3(512, 2), 256>>>(xyz, feature, wa, wb, wc);

    gemm_gn_kernel<0><<<dim3(512, 2), 256, sm0>>>(w0, gg0, gb0);  // gamma/beta unused
    reduce_stats_kernel<0><<<16, 256>>>();

    gemm_gn_kernel<1><<<dim3(512, 2), 256, sm1>>>(w1, gg0, gb0);
    reduce_stats_kernel<1><<<16, 256>>>();

    gemm_gn_kernel<2><<<dim3(512, 2), 512, sm2>>>(w2, gg1, gb1);
    reduce_stats_kernel<2><<<16, 256>>>();

    finalize_kernel<<<4096, 256>>>(gg2, gb2, out);
}

// round 2
// speedup vs baseline: 1.4240x; 1.4240x over previous
#include <cuda_runtime.h>

#define NPTS 4096
#define BQ_K 32
#define M_PER_B (NPTS * BQ_K)   // 131072 columns per batch
#define NBATCH 2

// ---------------- scratch (device globals; no allocations) ----------------
__device__ float g_x0[NBATCH * 13  * M_PER_B];   // fused features, [b][c][m]
__device__ float g_x1[NBATCH * 64  * M_PER_B];   // conv0 out (raw, pre-GN)
__device__ float g_x2[NBATCH * 64  * M_PER_B];   // conv1 out (raw, pre-GN)
__device__ float g_mx[NBATCH * 128 * NPTS];      // max over k of conv2 out (raw)
__device__ float g_mn[NBATCH * 128 * NPTS];      // min over k of conv2 out (raw)
__device__ float g_part[3][NBATCH * 512 * 8 * 2]; // per-block GN partial sums
__device__ float g_mr[3][NBATCH * 8 * 2];        // per-(b,group) mean/rstd

// ---------------- helpers ----------------
__device__ __forceinline__ float lo32(unsigned long long v) {
    return __uint_as_float((unsigned)(v & 0xffffffffull));
}
__device__ __forceinline__ float hi32(unsigned long long v) {
    return __uint_as_float((unsigned)(v >> 32));
}
// packed fp32x2 FMA (sm_103a): a = w*y + a, elementwise on two packed floats
__device__ __forceinline__ void ffma2(unsigned long long& a,
                                      unsigned long long w,
                                      unsigned long long y) {
    asm("fma.rn.f32x2 %0, %1, %2, %0;" : "+l"(a) : "l"(w), "l"(y));
}

__device__ __forceinline__ float angle3(float ax, float ay, float az,
                                        float bx, float by, float bz) {
    float cx = ay * bz - az * by;
    float cy = az * bx - ax * bz;
    float cz = ax * by - ay * bx;
    float s = cx * cx + cy * cy + cz * cz;
    float y = s > 0.f ? sqrtf(s) : 0.f;
    float x = ax * bx + ay * by + az * bz;
    if (y == 0.f && x == 0.f) return 0.f;
    return atan2f(y, x);
}

// ---------------- kernel 1: ball query + fused 13-ch features ----------------
__global__ void __launch_bounds__(256) ball_feat_kernel(
    const float* __restrict__ xyz, const float* __restrict__ feat,
    const float* __restrict__ wa, const float* __restrict__ wb,
    const float* __restrict__ wc)
{
    __shared__ float sx[NPTS * 3];  // 48KB
    const int b = blockIdx.y;
    const float* xb = xyz + (size_t)b * NPTS * 3;
    const float* fb = feat + (size_t)b * NPTS * 3;
    for (int i = threadIdx.x; i < NPTS * 3; i += 256) sx[i] = xb[i];
    __syncthreads();

    const int warp = threadIdx.x >> 5;
    const int lane = threadIdx.x & 31;
    const int i = blockIdx.x * 8 + warp;

    const float cx = sx[i * 3 + 0], cy = sx[i * 3 + 1], cz = sx[i * 3 + 2];
    const float R2 = (float)(0.1 * 0.1);

    int myj = 0;
    int found = 0;
    for (int jb = 0; jb < NPTS; jb += 32) {
        int j = jb + lane;
        float dx = sx[j * 3 + 0] - cx;
        float dy = sx[j * 3 + 1] - cy;
        float dz = sx[j * 3 + 2] - cz;
        float d2 = __fadd_rn(__fadd_rn(__fmul_rn(dx, dx), __fmul_rn(dy, dy)),
                             __fmul_rn(dz, dz));
        unsigned m = __ballot_sync(0xffffffffu, d2 <= R2);
        int cnt = __popc(m);
        if (lane >= found && lane < found + cnt) {
            int pos = __fns(m, 0, lane - found + 1);
            myj = jb + pos;
        }
        found += cnt;
        if (found >= BQ_K) break;
    }
    int j0 = __shfl_sync(0xffffffffu, myj, 0);
    if (lane >= found) myj = j0;

    float gx = sx[myj * 3 + 0], gy = sx[myj * 3 + 1], gz = sx[myj * 3 + 2];
    float nx = __ldg(fb + myj * 3 + 0), ny = __ldg(fb + myj * 3 + 1), nz = __ldg(fb + myj * 3 + 2);
    float rx = __ldg(fb + i * 3 + 0),  ry = __ldg(fb + i * 3 + 1),  rz = __ldg(fb + i * 3 + 2);
    float dx = gx - cx, dy = gy - cy, dz = gz - cz;
    float sq = dx * dx + dy * dy + dz * dz;
    float dist = sq > 0.f ? sqrtf(sq) : 0.f;
    float a1 = angle3(rx, ry, rz, dx, dy, dz);
    float a2 = angle3(nx, ny, nz, dx, dy, dz);
    float a3 = angle3(rx, ry, rz, nx, ny, nz);
    float A = __ldg(wa), Bv = __ldg(wb), Cv = __ldg(wc);

    float* o = g_x0 + (size_t)b * 13 * M_PER_B + (size_t)i * 32 + lane;
    o[0 * M_PER_B]  = A * cx;  o[1 * M_PER_B]  = A * cy;  o[2 * M_PER_B]  = A * cz;
    o[3 * M_PER_B]  = A * gx;  o[4 * M_PER_B]  = A * gy;  o[5 * M_PER_B]  = A * gz;
    o[6 * M_PER_B]  = Bv * dx; o[7 * M_PER_B]  = Bv * dy; o[8 * M_PER_B]  = Bv * dz;
    o[9 * M_PER_B]  = Bv * dist;
    o[10 * M_PER_B] = Cv * a1; o[11 * M_PER_B] = Cv * a2; o[12 * M_PER_B] = Cv * a3;
}

// ---------------- fused GEMM + (input GN/ReLU) + stats (+ max/min epilogue) ----
// Thread tile: 8 outputs x 8 columns. Warp = 8 outputs (one GN group for O=64).
template <int LAYER>
__global__ void __launch_bounds__(LAYER == 2 ? 512 : 256, LAYER == 2 ? 1 : 2)
gemm_gn_kernel(const float* __restrict__ W, const float* __restrict__ gamma,
               const float* __restrict__ beta)
{
    constexpr int C     = (LAYER == 0) ? 13 : 64;
    constexpr int O     = (LAYER == 2) ? 128 : 64;
    constexpr int NT    = (LAYER == 2) ? 512 : 256;
    constexpr int NW    = NT / 32;
    constexpr bool GN_IN = (LAYER > 0);
    constexpr bool LAST  = (LAYER == 2);

    extern __shared__ unsigned char smraw[];
    float2* Wp     = (float2*)smraw;                                 // [O*C] {w,w}
    float*  Xs     = (float*)(smraw + sizeof(float2) * O * C);       // [C][256]
    float*  sScale = Xs + C * 256;                                   // [64]
    float*  sShift = sScale + 64;                                    // [64]
    float*  sWsum  = sShift + 64;                                    // [NW*2]

    const int tid = threadIdx.x;
    const int b   = blockIdx.y;
    const int m0  = blockIdx.x * 256;

    for (int idx = tid; idx < O * C; idx += NT) {
        float w = W[idx];
        Wp[idx] = make_float2(w, w);
    }
    if (GN_IN && tid < C) {
        const float* mr = g_mr[LAYER - 1] + b * 16;
        int gg = tid >> 3;                 // C=64 here, 8 channels per group
        float s = mr[gg * 2 + 1] * gamma[tid];
        sScale[tid] = s;
        sShift[tid] = beta[tid] - mr[gg * 2] * s;
    }
    __syncthreads();

    // ---- stage X tile (vectorized, fused input-GN+ReLU) ----
    const float* xin = (LAYER == 0) ? g_x0 : ((LAYER == 1) ? g_x1 : g_x2);
    const float* xbp = xin + (size_t)b * C * M_PER_B + m0;
    for (int idx = tid; idx < C * 64; idx += NT) {
        int ci = idx >> 6;
        int c4 = (idx & 63) << 2;
        float4 v = *(const float4*)&xbp[(size_t)ci * M_PER_B + c4];
        if (GN_IN) {
            float s = sScale[ci], t = sShift[ci];
            v.x = fmaxf(s * v.x + t, 0.f);
            v.y = fmaxf(s * v.y + t, 0.f);
            v.z = fmaxf(s * v.z + t, 0.f);
            v.w = fmaxf(s * v.w + t, 0.f);
        }
        *(float4*)&Xs[ci * 256 + c4] = v;
    }
    __syncthreads();

    const int ob   = tid >> 5;      // warp id: owns outputs [8ob, 8ob+8)
    const int cg   = tid & 31;      // owns columns [cg*8, cg*8+8)
    const float* xcol = Xs + cg * 8;

    unsigned long long acc[8][4];
#pragma unroll
    for (int a = 0; a < 8; a++) {
        acc[a][0] = 0ull; acc[a][1] = 0ull; acc[a][2] = 0ull; acc[a][3] = 0ull;
    }

    if (C & 1) {   // layer 0, C=13: scalar weight path
#pragma unroll
        for (int i = 0; i < C; i++) {
            ulonglong2 ya = *(const ulonglong2*)&xcol[i * 256];
            ulonglong2 yb = *(const ulonglong2*)&xcol[i * 256 + 4];
#pragma unroll
            for (int oo = 0; oo < 8; oo++) {
                unsigned long long w =
                    *(const unsigned long long*)&Wp[(ob * 8 + oo) * C + i];
                ffma2(acc[oo][0], w, ya.x);
                ffma2(acc[oo][1], w, ya.y);
                ffma2(acc[oo][2], w, yb.x);
                ffma2(acc[oo][3], w, yb.y);
            }
        }
    } else {       // C=64: paired channels, LDS.128 weights
#pragma unroll 4
        for (int i = 0; i < C; i += 2) {
            ulonglong2 ya = *(const ulonglong2*)&xcol[i * 256];
            ulonglong2 yb = *(const ulonglong2*)&xcol[i * 256 + 4];
            ulonglong2 yc = *(const ulonglong2*)&xcol[i * 256 + 256];
            ulonglong2 yd = *(const ulonglong2*)&xcol[i * 256 + 260];
#pragma unroll
            for (int oo = 0; oo < 8; oo++) {
                ulonglong2 w = *(const ulonglong2*)&Wp[(ob * 8 + oo) * C + i];
                ffma2(acc[oo][0], w.x, ya.x);
                ffma2(acc[oo][1], w.x, ya.y);
                ffma2(acc[oo][2], w.x, yb.x);
                ffma2(acc[oo][3], w.x, yb.y);
                ffma2(acc[oo][0], w.y, yc.x);
                ffma2(acc[oo][1], w.y, yc.y);
                ffma2(acc[oo][2], w.y, yd.x);
                ffma2(acc[oo][3], w.y, yd.y);
            }
        }
    }

    // ---- epilogue ----
    if (!LAST) {
        float* xo = ((LAYER == 0) ? g_x1 : g_x2)
                    + (size_t)b * O * M_PER_B + m0 + cg * 8;
#pragma unroll
        for (int oo = 0; oo < 8; oo++) {
            float4 v0, v1;
            v0.x = lo32(acc[oo][0]); v0.y = hi32(acc[oo][0]);
            v0.z = lo32(acc[oo][1]); v0.w = hi32(acc[oo][1]);
            v1.x = lo32(acc[oo][2]); v1.y = hi32(acc[oo][2]);
            v1.z = lo32(acc[oo][3]); v1.w = hi32(acc[oo][3]);
            *(float4*)&xo[(size_t)(ob * 8 + oo) * M_PER_B]     = v0;
            *(float4*)&xo[(size_t)(ob * 8 + oo) * M_PER_B + 4] = v1;
        }
    } else {
        // columns m = m0 + cg*8 .. +7 all belong to n = blockIdx.x*8 + cg/4;
        // lanes with equal cg>>2 (4 lanes) cover the 32 k's of that n.
        int n = blockIdx.x * 8 + (cg >> 2);
#pragma unroll
        for (int oo = 0; oo < 8; oo++) {
            float v0 = lo32(acc[oo][0]), v1 = hi32(acc[oo][0]);
            float v2 = lo32(acc[oo][1]), v3 = hi32(acc[oo][1]);
            float v4 = lo32(acc[oo][2]), v5 = hi32(acc[oo][2]);
            float v6 = lo32(acc[oo][3]), v7 = hi32(acc[oo][3]);
            float mx = fmaxf(fmaxf(fmaxf(v0, v1), fmaxf(v2, v3)),
                             fmaxf(fmaxf(v4, v5), fmaxf(v6, v7)));
            float mn = fminf(fminf(fminf(v0, v1), fminf(v2, v3)),
                             fminf(fminf(v4, v5), fminf(v6, v7)));
            mx = fmaxf(mx, __shfl_xor_sync(0xffffffffu, mx, 1));
            mn = fminf(mn, __shfl_xor_sync(0xffffffffu, mn, 1));
            mx = fmaxf(mx, __shfl_xor_sync(0xffffffffu, mx, 2));
            mn = fminf(mn, __shfl_xor_sync(0xffffffffu, mn, 2));
            if ((cg & 3) == 0) {
                int o = ob * 8 + oo;
                g_mx[((size_t)b * O + o) * NPTS + n] = mx;
                g_mn[((size_t)b * O + o) * NPTS + n] = mn;
            }
        }
    }

    // ---- GN stats partials (warp covers one group for O=64, half for O=128) ----
    {
        float S = 0.f, Q = 0.f;
#pragma unroll
        for (int oo = 0; oo < 8; oo++) {
#pragma unroll
            for (int p = 0; p < 4; p++) {
                float v0 = lo32(acc[oo][p]), v1 = hi32(acc[oo][p]);
                S += v0 + v1;
                Q += v0 * v0 + v1 * v1;
            }
        }
#pragma unroll
        for (int d = 16; d > 0; d >>= 1) {
            S += __shfl_xor_sync(0xffffffffu, S, d);
            Q += __shfl_xor_sync(0xffffffffu, Q, d);
        }
        if ((tid & 31) == 0) {
            sWsum[ob * 2 + 0] = S;
            sWsum[ob * 2 + 1] = Q;
        }
    }
    __syncthreads();
    if (tid < 8) {
        float S, Q;
        if (O == 64) {                       // group g == warp g
            S = sWsum[tid * 2 + 0];
            Q = sWsum[tid * 2 + 1];
        } else {                             // group g = warps {2g, 2g+1}
            S = sWsum[(2 * tid) * 2 + 0] + sWsum[(2 * tid + 1) * 2 + 0];
            Q = sWsum[(2 * tid) * 2 + 1] + sWsum[(2 * tid + 1) * 2 + 1];
        }
        float* pp = g_part[LAYER] + (((size_t)b * gridDim.x + blockIdx.x) * 8 + tid) * 2;
        pp[0] = S;
        pp[1] = Q;
    }
}

// ---------------- per-(b,group) stats reduce ----------------
template <int LAYER>
__global__ void __launch_bounds__(256) reduce_stats_kernel()
{
    constexpr float INV = (LAYER == 2) ? (1.f / 2097152.f) : (1.f / 1048576.f);
    const int b = blockIdx.x >> 3, g = blockIdx.x & 7;
    __shared__ float sS[256], sQ[256];
    float S = 0.f, Q = 0.f;
    for (int mb = threadIdx.x; mb < 512; mb += 256) {
        const float* p = g_part[LAYER] + (((size_t)b * 512 + mb) * 8 + g) * 2;
        S += p[0];
        Q += p[1];
    }
    sS[threadIdx.x] = S; sQ[threadIdx.x] = Q;
    __syncthreads();
    for (int d = 128; d > 0; d >>= 1) {
        if (threadIdx.x < d) {
            sS[threadIdx.x] += sS[threadIdx.x + d];
            sQ[threadIdx.x] += sQ[threadIdx.x + d];
        }
        __syncthreads();
    }
    if (threadIdx.x == 0) {
        float mean = sS[0] * INV;
        float var  = sQ[0] * INV - mean * mean;
        g_mr[LAYER][b * 16 + g * 2 + 0] = mean;
        g_mr[LAYER][b * 16 + g * 2 + 1] = rsqrtf(var + 1e-5f);
    }
}

// ---------------- finalize ----------------
__global__ void __launch_bounds__(256) finalize_kernel(
    const float* __restrict__ gamma, const float* __restrict__ beta,
    float* __restrict__ out)
{
    int i = blockIdx.x * 256 + threadIdx.x;       // [b][o][n], 2*128*4096
    int o = (i >> 12) & 127;
    int b = i >> 19;
    int g = o >> 4;
    const float* mr = g_mr[2] + b * 16 + g * 2;
    float s = mr[1] * gamma[o];
    float t = beta[o] - mr[0] * s;
    float v = (s >= 0.f) ? (s * g_mx[i] + t) : (s * g_mn[i] + t);
    out[i] = fmaxf(v, 0.f);
    out[2 * 128 * NPTS + i] = v;
}

// ---------------- launch ----------------
extern "C" void kernel_launch(void* const* d_in, const int* in_sizes, int n_in,
                              void* d_out, int out_size)
{
    const float* feature = (const float*)d_in[0];
    const float* xyz     = (const float*)d_in[1];
    const float* w0  = (const float*)d_in[2];
    const float* gg0 = (const float*)d_in[3];
    const float* gb0 = (const float*)d_in[4];
    const float* w1  = (const float*)d_in[5];
    const float* gg1 = (const float*)d_in[6];
    const float* gb1 = (const float*)d_in[7];
    const float* w2  = (const float*)d_in[8];
    const float* gg2 = (const float*)d_in[9];
    const float* gb2 = (const float*)d_in[10];
    const float* wa  = (const float*)d_in[11];
    const float* wb  = (const float*)d_in[12];
    const float* wc  = (const float*)d_in[13];
    float* out = (float*)d_out;

    // dynamic smem: Wp(O*C*8) + Xs(C*256*4) + scale/shift(512) + sWsum(NW*8)
    const int sm0 = 64 * 13 * 8  + 13 * 256 * 4 + 512 + 8 * 8;
    const int sm1 = 64 * 64 * 8  + 64 * 256 * 4 + 512 + 8 * 8;
    const int sm2 = 128 * 64 * 8 + 64 * 256 * 4 + 512 + 16 * 8;
    cudaFuncSetAttribute(gemm_gn_kernel<0>, cudaFuncAttributeMaxDynamicSharedMemorySize, sm0);
    cudaFuncSetAttribute(gemm_gn_kernel<1>, cudaFuncAttributeMaxDynamicSharedMemorySize, sm1);
    cudaFuncSetAttribute(gemm_gn_kernel<2>, cudaFuncAttributeMaxDynamicSharedMemorySize, sm2);

    ball_feat_kernel<<<dim3(512, 2), 256>>>(xyz, feature, wa, wb, wc);

    gemm_gn_kernel<0><<<dim3(512, 2), 256, sm0>>>(w0, gg0, gb0);
    reduce_stats_kernel<0><<<16, 256>>>();

    gemm_gn_kernel<1><<<dim3(512, 2), 256, sm1>>>(w1, gg0, gb0);
    reduce_stats_kernel<1><<<16, 256>>>();

    gemm_gn_kernel<2><<<dim3(512, 2), 512, sm2>>>(w2, gg1, gb1);
    reduce_stats_kernel<2><<<16, 256>>>();

    finalize_kernel<<<4096, 256>>>(gg2, gb2, out);
}